// round 3
// baseline (speedup 1.0000x reference)
#include <cuda_runtime.h>

// GHM-C loss, single fused streaming pass.
//
// Identity used: weights are constant per histogram bin, so
//   pos_loss + neg_loss = sum_b w[b] * binsum[b]
// where binsum[b] = sum over in-bin elements of
//   log(pred)*pos + log(1-pred)*(valid-pos)*(1-hm)^4.
// w[b] depends only on global counts -> tiny epilogue kernel.
// num_pos==0 branch is redundant (pos_loss==0 there), so dropped.
//
// Shapes fixed: B=32, H=W=512 -> HW = 2^18.

static const int kHW  = 262144;
static const int kHW3 = 3 * 262144;

__device__ double g_binsum[10];
__device__ int    g_counts[10];
__device__ int    g_tot;

__global__ void ghm_init() {
    int t = threadIdx.x;
    if (t < 10) { g_binsum[t] = 0.0; g_counts[t] = 0; }
    if (t == 10) g_tot = 0;
}

__global__ void __launch_bounds__(256)
ghm_fused(const float* __restrict__ pred, const float* __restrict__ target, int nvec) {
    __shared__ float s_acc[8][10];
    __shared__ int   s_cnt[8][10];
    __shared__ int   s_tot[8];

    int tid = threadIdx.x;
    const float EDGE_TOP = 1.0f + 1e-6f;

    float acc[10];
#pragma unroll
    for (int k = 0; k < 10; k++) acc[k] = 0.0f;
    // byte-packed per-thread counts: c0 = bins0-3, c1 = bins4-7, c2 = bins8-9
    unsigned c0 = 0, c1 = 0, c2 = 0;
    int ctot = 0;

    int stride = gridDim.x * blockDim.x;
    for (int v = blockIdx.x * blockDim.x + tid; v < nvec; v += stride) {
        int i = v << 2;
        int b = i / kHW;            // power of two -> shift
        int j = i - b * kHW;
        int tb = b * kHW3 + j;
        float4 p  = *(const float4*)(pred + i);
        float4 hm = *(const float4*)(target + tb);
        float4 va = *(const float4*)(target + tb + kHW);
        float4 po = *(const float4*)(target + tb + 2 * kHW);
        const float* pp = (const float*)&p;
        const float* hh = (const float*)&hm;
        const float* vv = (const float*)&va;
        const float* ss = (const float*)&po;
#pragma unroll
        for (int k = 0; k < 4; k++) {
            float pv = pp[k], hv = hh[k], v1 = vv[k], sv = ss[k];
            float g  = fmaf(pv, v1, -sv);
            float ga = fabsf(g);
            bool validb = v1 > 0.0f;
            bool pin = validb && (ga < EDGE_TOP);
            ctot += validb ? 1 : 0;
            int idx = (int)(ga * 10.0f);
            idx = idx > 9 ? 9 : idx;

            // combined per-element loss term (weight factored out per-bin)
            float omh = 1.0f - hv;
            float nw  = omh * omh; nw *= nw;
            float neg = v1 - sv;
            float c   = __logf(pv) * sv + __logf(1.0f - pv) * (neg * nw);
            float cz  = pin ? c : 0.0f;
#pragma unroll
            for (int q = 0; q < 10; q++)
                if (idx == q) acc[q] += cz;

            unsigned inc = pin ? (1u << ((idx & 3) * 8)) : 0u;
            if (idx < 4)      c0 += inc;
            else if (idx < 8) c1 += inc;
            else              c2 += inc;
        }
    }

    // warp reduce: widen byte counters to 16-bit fields (max 28*32=896)
    unsigned e0 = c0 & 0x00FF00FFu;
    unsigned e1 = (c0 >> 8) & 0x00FF00FFu;
    unsigned e2 = c1 & 0x00FF00FFu;
    unsigned e3 = (c1 >> 8) & 0x00FF00FFu;
    unsigned e4 = (c2 & 0xFFu) | ((c2 & 0xFF00u) << 8);
#pragma unroll
    for (int o = 16; o > 0; o >>= 1) {
        e0   += __shfl_down_sync(0xffffffffu, e0, o);
        e1   += __shfl_down_sync(0xffffffffu, e1, o);
        e2   += __shfl_down_sync(0xffffffffu, e2, o);
        e3   += __shfl_down_sync(0xffffffffu, e3, o);
        e4   += __shfl_down_sync(0xffffffffu, e4, o);
        ctot += __shfl_down_sync(0xffffffffu, ctot, o);
#pragma unroll
        for (int k = 0; k < 10; k++)
            acc[k] += __shfl_down_sync(0xffffffffu, acc[k], o);
    }

    int wid = tid >> 5;
    if ((tid & 31) == 0) {
#pragma unroll
        for (int k = 0; k < 10; k++) s_acc[wid][k] = acc[k];
        s_cnt[wid][0] = (int)(e0 & 0xFFFFu);
        s_cnt[wid][1] = (int)(e1 & 0xFFFFu);
        s_cnt[wid][2] = (int)(e0 >> 16);
        s_cnt[wid][3] = (int)(e1 >> 16);
        s_cnt[wid][4] = (int)(e2 & 0xFFFFu);
        s_cnt[wid][5] = (int)(e3 & 0xFFFFu);
        s_cnt[wid][6] = (int)(e2 >> 16);
        s_cnt[wid][7] = (int)(e3 >> 16);
        s_cnt[wid][8] = (int)(e4 & 0xFFFFu);
        s_cnt[wid][9] = (int)(e4 >> 16);
        s_tot[wid] = ctot;
    }
    __syncthreads();
    if (tid < 10) {
        float a = 0.0f;
        int   c = 0;
#pragma unroll
        for (int w = 0; w < 8; w++) { a += s_acc[w][tid]; c += s_cnt[w][tid]; }
        atomicAdd(&g_binsum[tid], (double)a);
        atomicAdd(&g_counts[tid], c);
    } else if (tid == 10) {
        int t = 0;
#pragma unroll
        for (int w = 0; w < 8; w++) t += s_tot[w];
        atomicAdd(&g_tot, t);
    }
}

__global__ void ghm_final(float* out) {
    if (threadIdx.x == 0) {
        double tot = (double)max(g_tot, 1);
        int nn = 0;
#pragma unroll
        for (int k = 0; k < 10; k++) nn += (g_counts[k] > 0) ? 1 : 0;
        double nnf = (double)max(nn, 1);
        double sum = 0.0;
#pragma unroll
        for (int k = 0; k < 10; k++) {
            int c = g_counts[k];
            if (c > 0) {
                double w = (tot / (double)c) / nnf;
                sum += w * g_binsum[k];
            }
        }
        out[0] = (float)(-sum / tot);
    }
}

extern "C" void kernel_launch(void* const* d_in, const int* in_sizes, int n_in,
                              void* d_out, int out_size) {
    const float* pred   = (const float*)d_in[0];
    const float* target = (const float*)d_in[1];
    int npred = in_sizes[0];
    if (n_in >= 2 && in_sizes[1] < npred) {  // pred is the smaller tensor
        pred   = (const float*)d_in[1];
        target = (const float*)d_in[0];
        npred  = in_sizes[1];
    }
    int nvec = npred >> 2;

    const int blocks = 1184;
    const int threads = 256;

    ghm_init<<<1, 32>>>();
    ghm_fused<<<blocks, threads>>>(pred, target, nvec);
    ghm_final<<<1, 32>>>((float*)d_out);
}

// round 4
// speedup vs baseline: 2.2757x; 2.2757x over previous
#include <cuda_runtime.h>

// GHM-C loss, single fused streaming pass.
//
// Identity: weights are constant per histogram bin, so
//   pos_loss + neg_loss = sum_b w[b] * binsum[b],
//   binsum[b] = sum over in-bin elems of log(pred)*pos + log(1-pred)*(valid-pos)*(1-hm)^4.
// Also: in_bin == valid for this data (g<1 whenever valid), so tot = sum(counts).
// num_pos==0 branch is redundant (pos_loss==0 there).
//
// Per-bin sums go through per-warp SHARED float atomics (round-3's register
// array spilled to local memory and doubled runtime). Counts stay in
// byte-packed registers. Globals are reset by the final kernel so no init
// launch is needed (device globals are zero-initialized at load).
//
// Shapes fixed: B=32, H=W=512 -> HW = 2^18.

static const int kHW  = 262144;
static const int kHW3 = 3 * 262144;

__device__ double g_binsum[10];
__device__ int    g_counts[10];

__global__ void __launch_bounds__(256)
ghm_fused(const float* __restrict__ pred, const float* __restrict__ target, int nvec) {
    __shared__ float s_bin[8][10];   // per-warp bin sums
    __shared__ int   s_cnt[11];

    int tid = threadIdx.x;
    int wid = tid >> 5;
    if (tid < 80) ((float*)s_bin)[tid] = 0.0f;
    if (tid < 10) s_cnt[tid] = 0;
    __syncthreads();

    // byte-packed per-thread counts: c0 = bins0-3, c1 = bins4-7, c2 = bins8-9
    unsigned c0 = 0, c1 = 0, c2 = 0;

    int stride = gridDim.x * blockDim.x;
    for (int v = blockIdx.x * blockDim.x + tid; v < nvec; v += stride) {
        int i = v << 2;
        int b = i / kHW;            // power of two -> shift
        int j = i - b * kHW;
        int tb = b * kHW3 + j;
        float4 p  = *(const float4*)(pred + i);
        float4 hm = *(const float4*)(target + tb);
        float4 va = *(const float4*)(target + tb + kHW);
        float4 po = *(const float4*)(target + tb + 2 * kHW);
        const float* pp = (const float*)&p;
        const float* hh = (const float*)&hm;
        const float* vv = (const float*)&va;
        const float* ss = (const float*)&po;
#pragma unroll
        for (int k = 0; k < 4; k++) {
            float pv = pp[k], hv = hh[k], v1 = vv[k], sv = ss[k];
            bool pin = v1 > 0.0f;      // in_bin == valid (g<1 when valid)
            float g  = fmaf(pv, v1, -sv);
            float ga = fabsf(g);
            int idx = (int)(ga * 10.0f);
            idx = idx > 9 ? 9 : idx;

            if (pin) {
                // per-element loss term (bin weight factored out)
                float omh = 1.0f - hv;
                float nw  = omh * omh; nw *= nw;
                float neg = v1 - sv;
                float c   = __logf(pv) * sv + __logf(1.0f - pv) * (neg * nw);
                atomicAdd(&s_bin[wid][idx], c);
                unsigned inc = 1u << ((idx & 3) * 8);
                if (idx < 4)      c0 += inc;
                else if (idx < 8) c1 += inc;
                else              c2 += inc;
            }
        }
    }

    // warp reduce counters: widen bytes to 16-bit fields (max ~28*32=896)
    unsigned e0 = c0 & 0x00FF00FFu;
    unsigned e1 = (c0 >> 8) & 0x00FF00FFu;
    unsigned e2 = c1 & 0x00FF00FFu;
    unsigned e3 = (c1 >> 8) & 0x00FF00FFu;
    unsigned e4 = (c2 & 0xFFu) | ((c2 & 0xFF00u) << 8);
#pragma unroll
    for (int o = 16; o > 0; o >>= 1) {
        e0 += __shfl_down_sync(0xffffffffu, e0, o);
        e1 += __shfl_down_sync(0xffffffffu, e1, o);
        e2 += __shfl_down_sync(0xffffffffu, e2, o);
        e3 += __shfl_down_sync(0xffffffffu, e3, o);
        e4 += __shfl_down_sync(0xffffffffu, e4, o);
    }
    if ((tid & 31) == 0) {
        atomicAdd(&s_cnt[0], (int)(e0 & 0xFFFFu));
        atomicAdd(&s_cnt[1], (int)(e1 & 0xFFFFu));
        atomicAdd(&s_cnt[2], (int)(e0 >> 16));
        atomicAdd(&s_cnt[3], (int)(e1 >> 16));
        atomicAdd(&s_cnt[4], (int)(e2 & 0xFFFFu));
        atomicAdd(&s_cnt[5], (int)(e3 & 0xFFFFu));
        atomicAdd(&s_cnt[6], (int)(e2 >> 16));
        atomicAdd(&s_cnt[7], (int)(e3 >> 16));
        atomicAdd(&s_cnt[8], (int)(e4 & 0xFFFFu));
        atomicAdd(&s_cnt[9], (int)(e4 >> 16));
    }
    __syncthreads();
    if (tid < 10) {
        float a = 0.0f;
#pragma unroll
        for (int w = 0; w < 8; w++) a += s_bin[w][tid];
        atomicAdd(&g_binsum[tid], (double)a);
        atomicAdd(&g_counts[tid], s_cnt[tid]);
    }
}

__global__ void ghm_final(float* out) {
    if (threadIdx.x == 0) {
        int toti = 0, nn = 0;
#pragma unroll
        for (int k = 0; k < 10; k++) {
            toti += g_counts[k];
            nn   += (g_counts[k] > 0) ? 1 : 0;
        }
        double tot = (double)max(toti, 1);
        double nnf = (double)max(nn, 1);
        double sum = 0.0;
#pragma unroll
        for (int k = 0; k < 10; k++) {
            int c = g_counts[k];
            if (c > 0) sum += (tot / (double)c) / nnf * g_binsum[k];
        }
        out[0] = (float)(-sum / tot);
        // reset accumulators for the next graph replay
#pragma unroll
        for (int k = 0; k < 10; k++) { g_binsum[k] = 0.0; g_counts[k] = 0; }
    }
}

extern "C" void kernel_launch(void* const* d_in, const int* in_sizes, int n_in,
                              void* d_out, int out_size) {
    const float* pred   = (const float*)d_in[0];
    const float* target = (const float*)d_in[1];
    int npred = in_sizes[0];
    if (n_in >= 2 && in_sizes[1] < npred) {  // pred is the smaller tensor
        pred   = (const float*)d_in[1];
        target = (const float*)d_in[0];
        npred  = in_sizes[1];
    }
    int nvec = npred >> 2;

    ghm_fused<<<1184, 256>>>(pred, target, nvec);
    ghm_final<<<1, 32>>>((float*)d_out);
}

// round 7
// speedup vs baseline: 2.3184x; 1.0187x over previous
#include <cuda_runtime.h>

// GHM-C loss, fused streaming pass + small finalize kernel (two launches).
// [Bisect build: identical to the 34.8us round-4 WIN except __ldcs streaming
//  hints on the four main-loop loads. Single-launch last-block finalize is
//  under suspicion for the container failures and is removed pending this run.]
//
// Identity: weights are constant per histogram bin, so
//   pos_loss + neg_loss = sum_b w[b] * binsum[b],
//   binsum[b] = sum over in-bin elems of log(pred)*pos + log(1-pred)*(valid-pos)*(1-hm)^4.
// in_bin == valid for this data (g<1 whenever valid) -> tot = sum(counts).
// num_pos==0 branch redundant (pos_loss==0 there).
//
// Per-bin sums: per-warp SHARED float atomics (register array spills -> local).
// Counts: byte-packed registers + warp shuffle.
// ghm_final resets globals after reading so each graph replay starts clean
// (device globals are zero-initialized at load).
//
// Shapes fixed: B=32, H=W=512 -> HW = 2^18.

static const int kHW  = 262144;
static const int kHW3 = 3 * 262144;

__device__ double g_binsum[10];
__device__ int    g_counts[10];

__global__ void __launch_bounds__(256)
ghm_fused(const float* __restrict__ pred, const float* __restrict__ target, int nvec) {
    __shared__ float s_bin[8][10];   // per-warp bin sums
    __shared__ int   s_cnt[11];

    int tid = threadIdx.x;
    int wid = tid >> 5;
    if (tid < 80) ((float*)s_bin)[tid] = 0.0f;
    if (tid < 10) s_cnt[tid] = 0;
    __syncthreads();

    // byte-packed per-thread counts: c0 = bins0-3, c1 = bins4-7, c2 = bins8-9
    unsigned c0 = 0, c1 = 0, c2 = 0;

    int stride = gridDim.x * blockDim.x;
    for (int v = blockIdx.x * blockDim.x + tid; v < nvec; v += stride) {
        int i = v << 2;
        int b = i / kHW;            // power of two -> shift
        int j = i - b * kHW;
        int tb = b * kHW3 + j;
        float4 p  = __ldcs((const float4*)(pred + i));
        float4 hm = __ldcs((const float4*)(target + tb));
        float4 va = __ldcs((const float4*)(target + tb + kHW));
        float4 po = __ldcs((const float4*)(target + tb + 2 * kHW));
        const float* pp = (const float*)&p;
        const float* hh = (const float*)&hm;
        const float* vv = (const float*)&va;
        const float* ss = (const float*)&po;
#pragma unroll
        for (int k = 0; k < 4; k++) {
            float pv = pp[k], hv = hh[k], v1 = vv[k], sv = ss[k];
            bool pin = v1 > 0.0f;      // in_bin == valid (g<1 when valid)
            float g  = fmaf(pv, v1, -sv);
            float ga = fabsf(g);
            int idx = (int)(ga * 10.0f);
            idx = idx > 9 ? 9 : idx;

            if (pin) {
                // per-element loss term (bin weight factored out)
                float omh = 1.0f - hv;
                float nw  = omh * omh; nw *= nw;
                float neg = v1 - sv;
                float c   = __logf(pv) * sv + __logf(1.0f - pv) * (neg * nw);
                atomicAdd(&s_bin[wid][idx], c);
                unsigned inc = 1u << ((idx & 3) * 8);
                if (idx < 4)      c0 += inc;
                else if (idx < 8) c1 += inc;
                else              c2 += inc;
            }
        }
    }

    // warp reduce counters: widen bytes to 16-bit fields (max ~28*32=896)
    unsigned e0 = c0 & 0x00FF00FFu;
    unsigned e1 = (c0 >> 8) & 0x00FF00FFu;
    unsigned e2 = c1 & 0x00FF00FFu;
    unsigned e3 = (c1 >> 8) & 0x00FF00FFu;
    unsigned e4 = (c2 & 0xFFu) | ((c2 & 0xFF00u) << 8);
#pragma unroll
    for (int o = 16; o > 0; o >>= 1) {
        e0 += __shfl_down_sync(0xffffffffu, e0, o);
        e1 += __shfl_down_sync(0xffffffffu, e1, o);
        e2 += __shfl_down_sync(0xffffffffu, e2, o);
        e3 += __shfl_down_sync(0xffffffffu, e3, o);
        e4 += __shfl_down_sync(0xffffffffu, e4, o);
    }
    if ((tid & 31) == 0) {
        atomicAdd(&s_cnt[0], (int)(e0 & 0xFFFFu));
        atomicAdd(&s_cnt[1], (int)(e1 & 0xFFFFu));
        atomicAdd(&s_cnt[2], (int)(e0 >> 16));
        atomicAdd(&s_cnt[3], (int)(e1 >> 16));
        atomicAdd(&s_cnt[4], (int)(e2 & 0xFFFFu));
        atomicAdd(&s_cnt[5], (int)(e3 & 0xFFFFu));
        atomicAdd(&s_cnt[6], (int)(e2 >> 16));
        atomicAdd(&s_cnt[7], (int)(e3 >> 16));
        atomicAdd(&s_cnt[8], (int)(e4 & 0xFFFFu));
        atomicAdd(&s_cnt[9], (int)(e4 >> 16));
    }
    __syncthreads();
    if (tid < 10) {
        float a = 0.0f;
#pragma unroll
        for (int w = 0; w < 8; w++) a += s_bin[w][tid];
        atomicAdd(&g_binsum[tid], (double)a);
        atomicAdd(&g_counts[tid], s_cnt[tid]);
    }
}

__global__ void ghm_final(float* out) {
    if (threadIdx.x == 0) {
        int toti = 0, nn = 0;
#pragma unroll
        for (int k = 0; k < 10; k++) {
            toti += g_counts[k];
            nn   += (g_counts[k] > 0) ? 1 : 0;
        }
        double tot = (double)max(toti, 1);
        double nnf = (double)max(nn, 1);
        double sum = 0.0;
#pragma unroll
        for (int k = 0; k < 10; k++) {
            int c = g_counts[k];
            if (c > 0) sum += (tot / (double)c) / nnf * g_binsum[k];
        }
        out[0] = (float)(-sum / tot);
        // reset accumulators for the next graph replay
#pragma unroll
        for (int k = 0; k < 10; k++) { g_binsum[k] = 0.0; g_counts[k] = 0; }
    }
}

extern "C" void kernel_launch(void* const* d_in, const int* in_sizes, int n_in,
                              void* d_out, int out_size) {
    const float* pred   = (const float*)d_in[0];
    const float* target = (const float*)d_in[1];
    int npred = in_sizes[0];
    if (n_in >= 2 && in_sizes[1] < npred) {  // pred is the smaller tensor
        pred   = (const float*)d_in[1];
        target = (const float*)d_in[0];
        npred  = in_sizes[1];
    }
    int nvec = npred >> 2;

    ghm_fused<<<1184, 256>>>(pred, target, nvec);
    ghm_final<<<1, 32>>>((float*)d_out);
}

// round 8
// speedup vs baseline: 2.4039x; 1.0369x over previous
#include <cuda_runtime.h>

// GHM-C loss, single-kernel: fused streaming pass + last-block finalize.
//
// Identity: weights are constant per histogram bin, so
//   pos_loss + neg_loss = sum_b w[b] * binsum[b],
//   binsum[b] = sum over in-bin elems of log(pred)*pos + log(1-pred)*(valid-pos)*(1-hm)^4.
// in_bin == valid for this data (g<1 whenever valid) -> tot = sum(counts).
// num_pos==0 branch redundant (pos_loss==0 there).
//
// Per-bin sums: per-warp SHARED float atomics. Counts: byte-packed registers
// + warp shuffle. Finalize: last block (ticket + threadfence), warp-parallel
// across 10 lanes, then resets all globals so each graph replay starts clean
// (device globals are zero-initialized at load).
//
// Shapes fixed: B=32, H=W=512 -> HW = 2^18.

static const int kHW  = 262144;
static const int kHW3 = 3 * 262144;

__device__ double       g_binsum[10];
__device__ int          g_counts[10];
__device__ unsigned int g_done;

__global__ void __launch_bounds__(256)
ghm_fused(const float* __restrict__ pred, const float* __restrict__ target,
          int nvec, float* __restrict__ out) {
    __shared__ float s_bin[8][10];   // per-warp bin sums
    __shared__ int   s_cnt[11];
    __shared__ bool  s_last;

    int tid = threadIdx.x;
    int wid = tid >> 5;
    if (tid < 80) ((float*)s_bin)[tid] = 0.0f;
    if (tid < 10) s_cnt[tid] = 0;
    __syncthreads();

    // byte-packed per-thread counts: c0 = bins0-3, c1 = bins4-7, c2 = bins8-9
    unsigned c0 = 0, c1 = 0, c2 = 0;

    int stride = gridDim.x * blockDim.x;
    for (int v = blockIdx.x * blockDim.x + tid; v < nvec; v += stride) {
        int i = v << 2;
        int b = i / kHW;            // power of two -> shift
        int j = i - b * kHW;
        int tb = b * kHW3 + j;
        float4 p  = __ldcs((const float4*)(pred + i));
        float4 hm = __ldcs((const float4*)(target + tb));
        float4 va = __ldcs((const float4*)(target + tb + kHW));
        float4 po = __ldcs((const float4*)(target + tb + 2 * kHW));
        const float* pp = (const float*)&p;
        const float* hh = (const float*)&hm;
        const float* vv = (const float*)&va;
        const float* ss = (const float*)&po;
#pragma unroll
        for (int k = 0; k < 4; k++) {
            float pv = pp[k], hv = hh[k], v1 = vv[k], sv = ss[k];
            bool pin = v1 > 0.0f;      // in_bin == valid (g<1 when valid)
            float g  = fmaf(pv, v1, -sv);
            float ga = fabsf(g);
            int idx = (int)(ga * 10.0f);
            idx = idx > 9 ? 9 : idx;

            if (pin) {
                // per-element loss term (bin weight factored out)
                float omh = 1.0f - hv;
                float nw  = omh * omh; nw *= nw;
                float neg = v1 - sv;
                float c   = __logf(pv) * sv + __logf(1.0f - pv) * (neg * nw);
                atomicAdd(&s_bin[wid][idx], c);
                unsigned inc = 1u << ((idx & 3) * 8);
                if (idx < 4)      c0 += inc;
                else if (idx < 8) c1 += inc;
                else              c2 += inc;
            }
        }
    }

    // warp reduce counters: widen bytes to 16-bit fields (max ~28*32=896)
    unsigned e0 = c0 & 0x00FF00FFu;
    unsigned e1 = (c0 >> 8) & 0x00FF00FFu;
    unsigned e2 = c1 & 0x00FF00FFu;
    unsigned e3 = (c1 >> 8) & 0x00FF00FFu;
    unsigned e4 = (c2 & 0xFFu) | ((c2 & 0xFF00u) << 8);
#pragma unroll
    for (int o = 16; o > 0; o >>= 1) {
        e0 += __shfl_down_sync(0xffffffffu, e0, o);
        e1 += __shfl_down_sync(0xffffffffu, e1, o);
        e2 += __shfl_down_sync(0xffffffffu, e2, o);
        e3 += __shfl_down_sync(0xffffffffu, e3, o);
        e4 += __shfl_down_sync(0xffffffffu, e4, o);
    }
    if ((tid & 31) == 0) {
        atomicAdd(&s_cnt[0], (int)(e0 & 0xFFFFu));
        atomicAdd(&s_cnt[1], (int)(e1 & 0xFFFFu));
        atomicAdd(&s_cnt[2], (int)(e0 >> 16));
        atomicAdd(&s_cnt[3], (int)(e1 >> 16));
        atomicAdd(&s_cnt[4], (int)(e2 & 0xFFFFu));
        atomicAdd(&s_cnt[5], (int)(e3 & 0xFFFFu));
        atomicAdd(&s_cnt[6], (int)(e2 >> 16));
        atomicAdd(&s_cnt[7], (int)(e3 >> 16));
        atomicAdd(&s_cnt[8], (int)(e4 & 0xFFFFu));
        atomicAdd(&s_cnt[9], (int)(e4 >> 16));
    }
    __syncthreads();
    if (tid < 10) {
        float a = 0.0f;
#pragma unroll
        for (int w = 0; w < 8; w++) a += s_bin[w][tid];
        atomicAdd(&g_binsum[tid], (double)a);
        atomicAdd(&g_counts[tid], s_cnt[tid]);
    }
    __syncthreads();

    // ticket: last block to arrive finalizes
    if (tid == 0) {
        __threadfence();
        unsigned old = atomicAdd(&g_done, 1u);
        s_last = (old == (unsigned)gridDim.x - 1u);
    }
    __syncthreads();

    if (s_last && wid == 0) {
        __threadfence();   // all blocks' global atomics are visible
        int lane = tid;    // warp 0: lanes 0..31
        int    c = (lane < 10) ? g_counts[lane] : 0;
        double bs = (lane < 10) ? g_binsum[lane] : 0.0;

        // warp reductions: tot, n_nonempty
        int toti = c, nn = (c > 0) ? 1 : 0;
#pragma unroll
        for (int o = 16; o > 0; o >>= 1) {
            toti += __shfl_down_sync(0xffffffffu, toti, o);
            nn   += __shfl_down_sync(0xffffffffu, nn, o);
        }
        toti = __shfl_sync(0xffffffffu, toti, 0);
        nn   = __shfl_sync(0xffffffffu, nn, 0);

        double tot = (double)(toti > 1 ? toti : 1);
        double nnf = (double)(nn > 1 ? nn : 1);
        double term = (c > 0) ? (tot / (double)c) / nnf * bs : 0.0;
#pragma unroll
        for (int o = 16; o > 0; o >>= 1)
            term += __shfl_down_sync(0xffffffffu, term, o);

        if (lane == 0) out[0] = (float)(-term / tot);
        // reset accumulators + ticket for the next graph replay
        if (lane < 10) { g_binsum[lane] = 0.0; g_counts[lane] = 0; }
        __threadfence();
        if (lane == 0) g_done = 0u;
    }
}

extern "C" void kernel_launch(void* const* d_in, const int* in_sizes, int n_in,
                              void* d_out, int out_size) {
    const float* pred   = (const float*)d_in[0];
    const float* target = (const float*)d_in[1];
    int npred = in_sizes[0];
    if (n_in >= 2 && in_sizes[1] < npred) {  // pred is the smaller tensor
        pred   = (const float*)d_in[1];
        target = (const float*)d_in[0];
        npred  = in_sizes[1];
    }
    int nvec = npred >> 2;

    ghm_fused<<<1184, 256>>>(pred, target, nvec, (float*)d_out);
}